// round 8
// baseline (speedup 1.0000x reference)
#include <cuda_runtime.h>

// DPLoss: masked per-row MSE of (pred - log(alignment)), normalized by row
// length, then mean over batch.
//
// Inputs (metadata order):
//   d_in[0] = pred            float32 [B, T]
//   d_in[1] = alignment       float32 [B, T]
//   d_in[2] = token_lengths   int32   [B]
// Output: scalar float32.
//
// Design (R6): SINGLE kernel launch. R5 ncu showed the 64-float zeroing
// kernel alone costs 3.8us -> per-launch latency dominated the measurement.
// We fuse init + reduce + finalize via the last-CTA-done pattern:
//   - block partials atomicAdd into 64 device slots (no single-address hotspot)
//   - threadfence + arrival counter; the last block folds the slots into
//     d_out[0], then re-zeroes slots+counter so every graph replay sees the
//     same initial state (deterministic, capture-safe, no extra launches).

#define CHUNK_VECS 256          // float4 vectors per block (= 1024 elements)
#define BLOCK_THREADS 128
#define NSLOTS 64

__device__ float        g_slots[NSLOTS];   // zero-init at module load
__device__ unsigned int g_counter;         // zero-init at module load

__global__ __launch_bounds__(BLOCK_THREADS) void dploss_fused(
    const float* __restrict__ pred,
    const float* __restrict__ alignment,
    const int*   __restrict__ lens,
    float* __restrict__ out,
    int T, float inv_B, unsigned int nblocks)
{
    const int row = blockIdx.x;
    const int len = lens[row];
    const int nvec = (len + 3) >> 2;
    const int chunk0 = blockIdx.y * CHUNK_VECS;

    float block_sum_contrib = 0.0f;   // computed only by thread 0 below

    if (chunk0 < nvec) {
        const float4* __restrict__ p4 =
            reinterpret_cast<const float4*>(pred + (size_t)row * T);
        const float4* __restrict__ a4 =
            reinterpret_cast<const float4*>(alignment + (size_t)row * T);

        const int v0 = chunk0 + threadIdx.x;
        const int v1 = v0 + BLOCK_THREADS;
        const bool m0 = v0 < nvec;
        const bool m1 = v1 < nvec;

        // Front-load all global reads (up to 4 LDG.128 in flight per thread).
        float4 p0, a0, p1, a1;
        if (m0) { p0 = p4[v0]; a0 = a4[v0]; }
        if (m1) { p1 = p4[v1]; a1 = a4[v1]; }

        float acc = 0.0f;

        if (m0) {
            const int base = v0 << 2;
            if (base + 4 <= len) {
                float d0 = p0.x - __logf(a0.x);
                float d1 = p0.y - __logf(a0.y);
                float d2 = p0.z - __logf(a0.z);
                float d3 = p0.w - __logf(a0.w);
                acc = fmaf(d0, d0, acc);
                acc = fmaf(d1, d1, acc);
                acc = fmaf(d2, d2, acc);
                acc = fmaf(d3, d3, acc);
            } else {
                if (base + 0 < len) { float d = p0.x - __logf(a0.x); acc = fmaf(d, d, acc); }
                if (base + 1 < len) { float d = p0.y - __logf(a0.y); acc = fmaf(d, d, acc); }
                if (base + 2 < len) { float d = p0.z - __logf(a0.z); acc = fmaf(d, d, acc); }
                if (base + 3 < len) { float d = p0.w - __logf(a0.w); acc = fmaf(d, d, acc); }
            }
        }
        if (m1) {
            const int base = v1 << 2;
            if (base + 4 <= len) {
                float d0 = p1.x - __logf(a1.x);
                float d1 = p1.y - __logf(a1.y);
                float d2 = p1.z - __logf(a1.z);
                float d3 = p1.w - __logf(a1.w);
                acc = fmaf(d0, d0, acc);
                acc = fmaf(d1, d1, acc);
                acc = fmaf(d2, d2, acc);
                acc = fmaf(d3, d3, acc);
            } else {
                if (base + 0 < len) { float d = p1.x - __logf(a1.x); acc = fmaf(d, d, acc); }
                if (base + 1 < len) { float d = p1.y - __logf(a1.y); acc = fmaf(d, d, acc); }
                if (base + 2 < len) { float d = p1.z - __logf(a1.z); acc = fmaf(d, d, acc); }
                if (base + 3 < len) { float d = p1.w - __logf(a1.w); acc = fmaf(d, d, acc); }
            }
        }

        // ---- block reduction: warp shuffle, then smem across 4 warps ----
        #pragma unroll
        for (int off = 16; off > 0; off >>= 1)
            acc += __shfl_xor_sync(0xFFFFFFFFu, acc, off);

        __shared__ float warp_sums[4];
        const int wid = threadIdx.x >> 5;
        const int lid = threadIdx.x & 31;
        if (lid == 0) warp_sums[wid] = acc;
        __syncthreads();

        if (threadIdx.x == 0) {
            float s = warp_sums[0] + warp_sums[1] + warp_sums[2] + warp_sums[3];
            block_sum_contrib = s * inv_B / (float)len;
        }
    }

    // ---- epilogue: scatter partial, arrive, last block finalizes ----
    if (threadIdx.x == 0) {
        if (block_sum_contrib != 0.0f || chunk0 < nvec) {
            const int slot = (blockIdx.x * gridDim.y + blockIdx.y) & (NSLOTS - 1);
            atomicAdd(&g_slots[slot], block_sum_contrib);
        }
        __threadfence();   // slot writes visible before arrival
    }
    __syncthreads();       // all threads wait so the whole block can finalize

    __shared__ unsigned int s_prev;
    if (threadIdx.x == 0)
        s_prev = atomicAdd(&g_counter, 1u);
    __syncthreads();

    if (s_prev == nblocks - 1u) {
        // Last block: fold the 64 slots into the scalar, then reset device
        // state so the next graph replay starts clean.
        __threadfence();   // acquire: make all slot writes visible

        float v = (threadIdx.x < NSLOTS) ? g_slots[threadIdx.x] : 0.0f;
        #pragma unroll
        for (int off = 16; off > 0; off >>= 1)
            v += __shfl_xor_sync(0xFFFFFFFFu, v, off);

        __shared__ float ws[2];
        const int wid = threadIdx.x >> 5;
        const int lid = threadIdx.x & 31;
        if (wid < 2 && lid == 0) ws[wid] = v;
        __syncthreads();

        if (threadIdx.x == 0) {
            out[0] = ws[0] + ws[1];
            g_counter = 0u;                     // reset for next replay
        }
        if (threadIdx.x < NSLOTS)
            g_slots[threadIdx.x] = 0.0f;        // reset for next replay
    }
}

extern "C" void kernel_launch(void* const* d_in, const int* in_sizes, int n_in,
                              void* d_out, int out_size)
{
    const float* pred      = (const float*)d_in[0];
    const float* alignment = (const float*)d_in[1];
    const int*   lens      = (const int*)d_in[2];
    float*       out       = (float*)d_out;

    const int B = in_sizes[2];
    const int T = in_sizes[0] / B;

    const int nvec_total = T >> 2;                       // float4 per row
    const int chunks = (nvec_total + CHUNK_VECS - 1) / CHUNK_VECS;

    dim3 grid(B, chunks);
    dploss_fused<<<grid, BLOCK_THREADS>>>(pred, alignment, lens, out, T,
                                          1.0f / (float)B,
                                          (unsigned int)(B * chunks));
}

// round 9
// speedup vs baseline: 1.1373x; 1.1373x over previous
#include <cuda_runtime.h>

// DPLoss: masked per-row MSE of (pred - log(alignment)), normalized by row
// length, then mean over batch.
//
// Inputs (metadata order):
//   d_in[0] = pred            float32 [B, T]
//   d_in[1] = alignment       float32 [B, T]
//   d_in[2] = token_lengths   int32   [B]
// Output: scalar float32.
//
// Design (R9): persistent-style single launch. R8 showed 8192 tiny blocks
// each paying threadfence + counter atomic + ramp against only 8KB of loads
// -> latency-bound at 27% DRAM. Now: fixed grid of 1480 blocks (10/SM, one
// wave), each grid-strides over (row, half-row chunk) work items, skipping
// chunks beyond the row's valid length. One epilogue per BLOCK (1480 total,
// was 8192). Per-thread accumulator carries across chunks with the per-row
// 1/len weight folded in multiplicatively (exact by linearity).

#define CHUNK_VECS 256          // float4 vectors per chunk (= 1024 elements)
#define BLOCK_THREADS 128
#define NSLOTS 64
#define NBLOCKS 1480            // 10 per SM on 148 SMs, single wave

__device__ float        g_slots[NSLOTS];   // zero-init at module load
__device__ unsigned int g_counter;         // zero-init at module load

__global__ __launch_bounds__(BLOCK_THREADS) void dploss_persistent(
    const float* __restrict__ pred,
    const float* __restrict__ alignment,
    const int*   __restrict__ lens,
    float* __restrict__ out,
    int T, int chunks_per_row, int total_chunks,
    float inv_B, unsigned int nblocks)
{
    float acc = 0.0f;   // running, already scaled by inv_B/len per chunk

    for (int c = blockIdx.x; c < total_chunks; c += nblocks) {
        const int row    = c / chunks_per_row;
        const int chunk0 = (c - row * chunks_per_row) * CHUNK_VECS;

        const int len  = __ldg(lens + row);
        const int nvec = (len + 3) >> 2;
        if (chunk0 >= nvec) continue;                  // dead chunk: 1 cheap load

        const float4* __restrict__ p4 =
            reinterpret_cast<const float4*>(pred + (size_t)row * T);
        const float4* __restrict__ a4 =
            reinterpret_cast<const float4*>(alignment + (size_t)row * T);

        const int v0 = chunk0 + threadIdx.x;
        const int v1 = v0 + BLOCK_THREADS;
        const bool m0 = v0 < nvec;
        const bool m1 = v1 < nvec;

        // Front-load all global reads (up to 4 LDG.128 in flight / thread).
        float4 p0, a0, p1, a1;
        if (m0) { p0 = p4[v0]; a0 = a4[v0]; }
        if (m1) { p1 = p4[v1]; a1 = a4[v1]; }

        float cs = 0.0f;   // this chunk's per-thread partial (unscaled)

        if (m0) {
            const int base = v0 << 2;
            if (base + 4 <= len) {
                float d0 = p0.x - __logf(a0.x);
                float d1 = p0.y - __logf(a0.y);
                float d2 = p0.z - __logf(a0.z);
                float d3 = p0.w - __logf(a0.w);
                cs = fmaf(d0, d0, cs);
                cs = fmaf(d1, d1, cs);
                cs = fmaf(d2, d2, cs);
                cs = fmaf(d3, d3, cs);
            } else {
                if (base + 0 < len) { float d = p0.x - __logf(a0.x); cs = fmaf(d, d, cs); }
                if (base + 1 < len) { float d = p0.y - __logf(a0.y); cs = fmaf(d, d, cs); }
                if (base + 2 < len) { float d = p0.z - __logf(a0.z); cs = fmaf(d, d, cs); }
                if (base + 3 < len) { float d = p0.w - __logf(a0.w); cs = fmaf(d, d, cs); }
            }
        }
        if (m1) {
            const int base = v1 << 2;
            if (base + 4 <= len) {
                float d0 = p1.x - __logf(a1.x);
                float d1 = p1.y - __logf(a1.y);
                float d2 = p1.z - __logf(a1.z);
                float d3 = p1.w - __logf(a1.w);
                cs = fmaf(d0, d0, cs);
                cs = fmaf(d1, d1, cs);
                cs = fmaf(d2, d2, cs);
                cs = fmaf(d3, d3, cs);
            } else {
                if (base + 0 < len) { float d = p1.x - __logf(a1.x); cs = fmaf(d, d, cs); }
                if (base + 1 < len) { float d = p1.y - __logf(a1.y); cs = fmaf(d, d, cs); }
                if (base + 2 < len) { float d = p1.z - __logf(a1.z); cs = fmaf(d, d, cs); }
                if (base + 3 < len) { float d = p1.w - __logf(a1.w); cs = fmaf(d, d, cs); }
            }
        }

        // fold per-row weight in now (linear, exact)
        acc = fmaf(cs, inv_B / (float)len, acc);
    }

    // ---- one block reduction + one scatter atomic per block ----
    #pragma unroll
    for (int off = 16; off > 0; off >>= 1)
        acc += __shfl_xor_sync(0xFFFFFFFFu, acc, off);

    __shared__ float warp_sums[4];
    const int wid = threadIdx.x >> 5;
    const int lid = threadIdx.x & 31;
    if (lid == 0) warp_sums[wid] = acc;
    __syncthreads();

    if (threadIdx.x == 0) {
        float s = warp_sums[0] + warp_sums[1] + warp_sums[2] + warp_sums[3];
        atomicAdd(&g_slots[blockIdx.x & (NSLOTS - 1)], s);
        __threadfence();                       // slot write visible first
    }
    __syncthreads();

    __shared__ unsigned int s_prev;
    if (threadIdx.x == 0)
        s_prev = atomicAdd(&g_counter, 1u);
    __syncthreads();

    if (s_prev == nblocks - 1u) {
        // Last block folds slots -> scalar, then resets device state so the
        // next graph replay starts clean.
        __threadfence();

        float v = (threadIdx.x < NSLOTS) ? g_slots[threadIdx.x] : 0.0f;
        #pragma unroll
        for (int off = 16; off > 0; off >>= 1)
            v += __shfl_xor_sync(0xFFFFFFFFu, v, off);

        __shared__ float ws[2];
        if (wid < 2 && lid == 0) ws[wid] = v;
        __syncthreads();

        if (threadIdx.x == 0) {
            out[0] = ws[0] + ws[1];
            g_counter = 0u;
        }
        if (threadIdx.x < NSLOTS)
            g_slots[threadIdx.x] = 0.0f;
    }
}

extern "C" void kernel_launch(void* const* d_in, const int* in_sizes, int n_in,
                              void* d_out, int out_size)
{
    const float* pred      = (const float*)d_in[0];
    const float* alignment = (const float*)d_in[1];
    const int*   lens      = (const int*)d_in[2];
    float*       out       = (float*)d_out;

    const int B = in_sizes[2];
    const int T = in_sizes[0] / B;

    const int nvec_total     = T >> 2;                             // float4 / row
    const int chunks_per_row = (nvec_total + CHUNK_VECS - 1) / CHUNK_VECS;
    const int total_chunks   = B * chunks_per_row;

    int nblocks = NBLOCKS;
    if (nblocks > total_chunks) nblocks = total_chunks;

    dploss_persistent<<<nblocks, BLOCK_THREADS>>>(
        pred, alignment, lens, out, T, chunks_per_row, total_chunks,
        1.0f / (float)B, (unsigned int)nblocks);
}